// round 11
// baseline (speedup 1.0000x reference)
#include <cuda_runtime.h>
#include <cuda_bf16.h>
#include <math.h>
#include <stdint.h>

#define ZTOT  65536
#define KTOT  204
#define NPATH 60
#define NOUT  324
#define SEGP  208            // per-segment padding (204 + 4)
#define KP2   624            // K' = 3 * 208
#define CH    48             // k' per chunk
#define NCH   13             // 624 / 48
#define NBP   384

// ---------------- scratch ----------------
__device__ uint4 g_Fhi4[(size_t)ZTOT * 32];           // [z][256] bf16 hi plane
__device__ uint4 g_Flo4[(size_t)ZTOT * 32];           // [z][256] bf16 lo plane
__device__ __align__(16) __nv_bfloat16 g_B[NBP * KP2];

// ---------------- helpers ----------------
__device__ __forceinline__ uint32_t smem_u32(const void* p) {
  uint32_t a;
  asm("{ .reg .u64 t; cvta.to.shared.u64 t, %1; cvt.u32.u64 %0, t; }"
      : "=r"(a) : "l"(p));
  return a;
}
__device__ __forceinline__ void cp16(uint32_t smaddr, const void* gptr) {
  asm volatile("cp.async.cg.shared.global [%0], [%1], 16;"
               :: "r"(smaddr), "l"(gptr) : "memory");
}
__device__ __forceinline__ void ldm_x4(uint32_t* r, uint32_t addr) {
  asm volatile("ldmatrix.sync.aligned.m8n8.x4.shared.b16 {%0,%1,%2,%3}, [%4];"
               : "=r"(r[0]), "=r"(r[1]), "=r"(r[2]), "=r"(r[3]) : "r"(addr));
}
__device__ __forceinline__ void mma16816(float* d, const uint32_t* a,
                                         const uint32_t* b) {
  asm volatile(
      "mma.sync.aligned.m16n8k16.row.col.f32.bf16.bf16.f32 "
      "{%0,%1,%2,%3}, {%4,%5,%6,%7}, {%8,%9}, {%0,%1,%2,%3};"
      : "+f"(d[0]), "+f"(d[1]), "+f"(d[2]), "+f"(d[3])
      : "r"(a[0]), "r"(a[1]), "r"(a[2]), "r"(a[3]), "r"(b[0]), "r"(b[1]));
}
__device__ __forceinline__ unsigned long long ffma2(unsigned long long a,
                                                    unsigned long long b,
                                                    unsigned long long c) {
  unsigned long long d;
  asm("fma.rn.f32x2 %0, %1, %2, %3;" : "=l"(d) : "l"(a), "l"(b), "l"(c));
  return d;
}
__device__ __forceinline__ unsigned long long pack2(float lo, float hi) {
  unsigned long long d;
  asm("mov.b64 %0, {%1, %2};" : "=l"(d) : "f"(lo), "f"(hi));
  return d;
}
__device__ __forceinline__ void unpack2(float& lo, float& hi,
                                        unsigned long long v) {
  asm("mov.b64 {%0, %1}, %2;" : "=f"(lo), "=f"(hi) : "l"(v));
}

// ---------------------------------------------------------------------------
// Kernel 1 (fused): radial MLP + SH -> bf16 hi/lo planes [z][256].
// MLP stages in packed fma.rn.f32x2 (halved FMA instruction count).
// ---------------------------------------------------------------------------
__global__ __launch_bounds__(128, 3) void feat_kernel(
    const float* __restrict__ r,  const float* __restrict__ W1,
    const float* __restrict__ b1, const float* __restrict__ W2,
    const float* __restrict__ b2) {
  extern __shared__ float sm[];
  float* sW1t = sm;                      // [64][68] transposed
  float* sW2  = sm + 4352;               // [64][60]
  float* sb1  = sm + 8192;
  float* sb2  = sm + 8256;
  float* sB   = sm + 8320;               // union: basis [64][128] / staging
  uint32_t* stg = (uint32_t*)sB;         // 2 planes x [128][33] uint32
  const int tid = threadIdx.x;

  #pragma unroll
  for (int i = 0; i < 32; ++i) {
    int idx = tid + i * 128;
    int j = idx >> 6, h = idx & 63;
    sW1t[h * 68 + j] = W1[idx];
  }
  #pragma unroll
  for (int i = 0; i < 30; ++i) sW2[tid + i*128] = W2[tid + i*128];
  if (tid < 64) sb1[tid] = b1[tid];
  if (tid < 60) sb2[tid] = b2[tid];
  __syncthreads();

  const int zb = blockIdx.x * 128;
  const int z = zb + tid;
  const float rx = r[3*z+0], ry = r[3*z+1], rz = r[3*z+2];
  const float rad = sqrtf(rx*rx + ry*ry + rz*rz);
  const float inv = 1.0f / (rad + 1e-12f);
  const float x = rx*inv, y = ry*inv, zc = rz*inv;

  float Y[9];
  Y[0] = 0.28209479177387814f;
  Y[1] = 0.4886025119029199f * y;
  Y[2] = 0.4886025119029199f * zc;
  Y[3] = 0.4886025119029199f * x;
  Y[4] = 1.0925484305920792f * x * y;
  Y[5] = 1.0925484305920792f * y * zc;
  Y[6] = 0.31539156525252005f * (3.0f*zc*zc - 1.0f);
  Y[7] = 1.0925484305920792f * x * zc;
  Y[8] = 0.5462742152960396f * (x*x - y*y);

  {  // radial basis, factorized (3 expf)
    const float DLT = 3.5f / 63.0f;
    int m = (int)floorf(rad / DLT + 0.5f);
    m = (m < 0) ? 0 : ((m > 63) ? 63 : m);
    const float u = rad - DLT * (float)m;
    const float A   = expf(-4.0f * u * u);
    const float tdn = expf(-0.44444444f * u);
    const float tup = expf( 0.44444444f * u);
    const float G1 = 0.98773021f;
    const float W  = 0.97561098f;
    sB[m*128 + tid] = A;
    float P = A, q = tdn * G1;
    for (int j = m - 1; j >= 0; --j) { P *= q; q *= W; sB[j*128 + tid] = P; }
    P = A; q = tup * G1;
    for (int j = m + 1; j < 64; ++j) { P *= q; q *= W; sB[j*128 + tid] = P; }
  }
  __syncthreads();

  // basis pairs -> packed registers
  unsigned long long Bu[32];
  #pragma unroll
  for (int q = 0; q < 32; ++q)
    Bu[q] = pack2(sB[(2*q)*128 + tid], sB[(2*q+1)*128 + tid]);

  // packed R accumulators
  unsigned long long Ru[30];
  #pragma unroll
  for (int q = 0; q < 30; ++q) Ru[q] = pack2(sb2[2*q], sb2[2*q+1]);

  #pragma unroll 4
  for (int h = 0; h < 64; ++h) {
    unsigned long long aA = 0ull, aB = 0ull;
    const float bias = sb1[h];
    #pragma unroll
    for (int q = 0; q < 16; ++q) {
      ulonglong2 w = *(const ulonglong2*)&sW1t[h*68 + q*4];
      aA = ffma2(Bu[2*q],   w.x, aA);
      aB = ffma2(Bu[2*q+1], w.y, aB);
    }
    float f0, f1, f2, f3;
    unpack2(f0, f1, aA);
    unpack2(f2, f3, aB);
    const float a = fmaxf(bias + ((f0 + f1) + (f2 + f3)), 0.0f);
    const unsigned long long ap = pack2(a, a);
    #pragma unroll
    for (int q = 0; q < 15; ++q) {
      ulonglong2 w = *(const ulonglong2*)&sW2[h*60 + q*4];
      Ru[2*q]   = ffma2(ap, w.x, Ru[2*q]);
      Ru[2*q+1] = ffma2(ap, w.y, Ru[2*q+1]);
    }
  }

  float R[NPATH];
  #pragma unroll
  for (int q = 0; q < 30; ++q) unpack2(R[2*q], R[2*q+1], Ru[q]);

  // emit bf16 hi/lo planes in 4 chunks of 64 k
  constexpr int LF[15]   = {0,1,2,1,0,1,2,1,2,2,1,2,0,1,2};
  constexpr int GOFF[15] = {0,4,16,36,48,52,64,84,96,116,136,148,168,172,184};
  __nv_bfloat16* stHi = (__nv_bfloat16*)stg;              // [128][66]
  __nv_bfloat16* stLo = (__nv_bfloat16*)(stg + 128*33);

  #pragma unroll
  for (int c = 0; c < 4; ++c) {
    __syncthreads();
    if (c == 3) {
      #pragma unroll
      for (int w = 6; w < 32; ++w) {
        stg[tid*33 + w] = 0u;
        stg[128*33 + tid*33 + w] = 0u;
      }
    }
    #pragma unroll
    for (int p = 0; p < NPATH; ++p) {
      const int l  = LF[p >> 2];
      const int yo = (l == 0) ? 0 : ((l == 1) ? 1 : 4);
      const int kb = GOFF[p >> 2] + (p & 3) * (2*l + 1);
      #pragma unroll
      for (int mm = 0; mm < 2*l + 1; ++mm) {
        const int k = kb + mm;
        if (k >= c*64 && k < c*64 + 64) {
          const int kk = k - c*64;
          float f = R[p] * Y[yo + mm];
          __nv_bfloat16 hi = __float2bfloat16(f);
          __nv_bfloat16 lo = __float2bfloat16(f - __bfloat162float(hi));
          stHi[tid*66 + kk] = hi;
          stLo[tid*66 + kk] = lo;
        }
      }
    }
    __syncthreads();
    #pragma unroll
    for (int it = 0; it < 16; ++it) {
      int i = tid + it * 128;
      int plane = i >> 10;
      int j = i & 1023;
      int row = j >> 3, q = j & 7;
      const uint32_t* src = stg + plane*(128*33) + row*33 + q*4;
      uint4 v; v.x = src[0]; v.y = src[1]; v.z = src[2]; v.w = src[3];
      (plane ? g_Flo4 : g_Fhi4)[(size_t)(zb + row) * 32 + c*8 + q] = v;
    }
  }
}

// ---------------------------------------------------------------------------
// Kernel 2: pack B = cg^T, segments {hi, lo, hi} at offsets 0/208/416
// ---------------------------------------------------------------------------
__global__ void prepB_kernel(const float* __restrict__ cg) {
  const int n = blockIdx.x;
  for (int kp = threadIdx.x; kp < KP2; kp += blockDim.x) {
    const int seg = kp / SEGP;
    const int k = kp - seg * SEGP;
    float v = (n < NOUT && k < KTOT) ? cg[k * NOUT + n] : 0.0f;
    __nv_bfloat16 hi = __float2bfloat16(v);
    __nv_bfloat16 lo = __float2bfloat16(v - __bfloat162float(hi));
    g_B[n * KP2 + kp] = (seg == 1) ? lo : hi;
  }
}

// ---------------------------------------------------------------------------
// Kernel 3: mma.sync bf16 GEMM, K'=624, 13 chunks of k48, 512 threads,
// 4x4 warp grid (warp tile 32x32), 3-stage cp.async ring, 112B rows.
// Warp-level skip of column groups >= NOUT (pad columns cost no HMMA).
// ---------------------------------------------------------------------------
#define ABUF 14336           // 128 * 112
#define BBUF 14336
#define STGN 3
__global__ __launch_bounds__(512) void mma_kernel(float* __restrict__ out) {
  extern __shared__ char smem[];
  const uint32_t sb = smem_u32(smem);
  const int tid = threadIdx.x;
  const int w = tid >> 5, lane = tid & 31;
  const int wm = w >> 2, wn = w & 3;           // 4 x 4 warp grid
  const int jb = blockIdx.x * 128;
  const int zb = blockIdx.y * 128;

  // column-group activity (static per warp)
  const bool wactive = (jb + wn*32) < NOUT;
  const bool g16[2] = { (jb + wn*32)      < NOUT,    // cols [0,16)
                        (jb + wn*32 + 16) < NOUT };  // cols [16,32)
  const bool g8[4]  = { (jb + wn*32)      < NOUT,
                        (jb + wn*32 + 8)  < NOUT,
                        (jb + wn*32 + 16) < NOUT,
                        (jb + wn*32 + 24) < NOUT };

  auto issue = [&](int c, int buf) {
    const uint32_t base = sb + buf * (ABUF + BBUF);
    const char* Bb = (const char*)g_B;
    #pragma unroll
    for (int it = 0; it < 3; ++it) {
      int i = tid + it * 512;                  // 0..1535
      int half = i >= 768;                     // 0: A, 1: B
      int j = i - half * 768;
      int row = j / 6, quad = j - row * 6;
      int kp = c * CH + quad * 8;
      uint32_t dst = base + half * ABUF + row * 112 + quad * 16;
      if (half) {
        cp16(dst, Bb + (size_t)(jb + row) * (KP2*2) + kp * 2);
      } else {
        int seg = (kp >= 2*SEGP) ? 2 : (kp >= SEGP ? 1 : 0);
        int kk = kp - seg * SEGP;
        const char* Asrc = (const char*)(seg == 2 ? g_Flo4 : g_Fhi4)
                           + (size_t)(zb + row) * 512 + kk * 2;
        cp16(dst, Asrc);
      }
    }
    asm volatile("cp.async.commit_group;" ::: "memory");
  };

  float acc[2][4][4];
  #pragma unroll
  for (int mt = 0; mt < 2; ++mt)
    #pragma unroll
    for (int nt = 0; nt < 4; ++nt)
      #pragma unroll
      for (int q = 0; q < 4; ++q) acc[mt][nt][q] = 0.0f;

  issue(0, 0);
  issue(1, 1);

  for (int c = 0; c < NCH; ++c) {
    if (c >= NCH - 2)
      asm volatile("cp.async.wait_group 0;" ::: "memory");
    else
      asm volatile("cp.async.wait_group 1;" ::: "memory");
    __syncthreads();

    if (c + 2 < NCH) issue(c + 2, (c + 2) % STGN);

    if (wactive) {
      const uint32_t aBase = sb + (c % STGN) * (ABUF + BBUF);
      const uint32_t bBase = aBase + ABUF;

      #pragma unroll
      for (int ks = 0; ks < 3; ++ks) {
        uint32_t afr[2][4];
        #pragma unroll
        for (int mt = 0; mt < 2; ++mt) {
          uint32_t addr = aBase + (wm*32 + mt*16 + (lane & 15)) * 112
                        + ks*32 + (lane >> 4) * 16;
          ldm_x4(afr[mt], addr);
        }
        uint32_t bfr[8];
        #pragma unroll
        for (int nt = 0; nt < 2; ++nt) {
          if (g16[nt]) {
            uint32_t addr = bBase
                + (wn*32 + nt*16 + ((lane >> 4) << 3) + (lane & 7)) * 112
                + ks*32 + ((lane >> 3) & 1) * 16;
            ldm_x4(&bfr[nt * 4], addr);
          }
        }
        #pragma unroll
        for (int mt = 0; mt < 2; ++mt)
          #pragma unroll
          for (int nt = 0; nt < 4; ++nt)
            if (g8[nt]) mma16816(acc[mt][nt], afr[mt], &bfr[nt * 2]);
      }
    }
  }

  // epilogue
  const int r0 = lane >> 2;
  const int c2 = (lane & 3) * 2;
  #pragma unroll
  for (int mt = 0; mt < 2; ++mt) {
    #pragma unroll
    for (int nt = 0; nt < 4; ++nt) {
      const int col = jb + wn*32 + nt*8 + c2;
      if (col < NOUT) {
        const int zr = zb + wm*32 + mt*16 + r0;
        *(float2*)&out[(size_t)zr * NOUT + col] =
            make_float2(acc[mt][nt][0], acc[mt][nt][1]);
        *(float2*)&out[(size_t)(zr + 8) * NOUT + col] =
            make_float2(acc[mt][nt][2], acc[mt][nt][3]);
      }
    }
  }
}

// ---------------------------------------------------------------------------
extern "C" void kernel_launch(void* const* d_in, const int* in_sizes, int n_in,
                              void* d_out, int out_size) {
  const float* r  = (const float*)d_in[0];
  const float* W1 = (const float*)d_in[1];
  const float* b1 = (const float*)d_in[2];
  const float* W2 = (const float*)d_in[3];
  const float* b2 = (const float*)d_in[4];
  const float* cg = (const float*)d_in[5];
  float* out = (float*)d_out;

  const int smem1 = (4352 + 3840 + 128 + 8448) * 4;     // 67072 B
  const int smem3 = STGN * (ABUF + BBUF);               // 86016 B
  cudaFuncSetAttribute(feat_kernel,
      cudaFuncAttributeMaxDynamicSharedMemorySize, smem1);
  cudaFuncSetAttribute(mma_kernel,
      cudaFuncAttributeMaxDynamicSharedMemorySize, smem3);

  feat_kernel<<<ZTOT/128, 128, smem1>>>(r, W1, b1, W2, b2);
  prepB_kernel<<<NBP, 224>>>(cg);
  mma_kernel<<<dim3(3, ZTOT/128), 512, smem3>>>(out);
}

// round 12
// speedup vs baseline: 1.2479x; 1.2479x over previous
#include <cuda_runtime.h>
#include <cuda_bf16.h>
#include <math.h>
#include <stdint.h>

#define ZTOT  65536
#define KTOT  204
#define NPATH 60
#define NOUT  324
#define SEGP  208            // per-segment padding (204 + 4)
#define KP2   624            // K' = 3 * 208
#define CH    48             // k' per chunk
#define NCH   13             // 624 / 48
#define NBP   384
#define STGN  3
#define ABUF  14336          // 128 * 112

// ---------------- scratch ----------------
__device__ uint4 g_Fhi4[(size_t)ZTOT * 32];           // [z][256] bf16 hi plane
__device__ uint4 g_Flo4[(size_t)ZTOT * 32];           // [z][256] bf16 lo plane
__device__ __align__(16) __nv_bfloat16 g_B[NBP * KP2];

// ---------------- helpers ----------------
__device__ __forceinline__ uint32_t smem_u32(const void* p) {
  uint32_t a;
  asm("{ .reg .u64 t; cvta.to.shared.u64 t, %1; cvt.u32.u64 %0, t; }"
      : "=r"(a) : "l"(p));
  return a;
}
__device__ __forceinline__ void cp16(uint32_t smaddr, const void* gptr) {
  asm volatile("cp.async.cg.shared.global [%0], [%1], 16;"
               :: "r"(smaddr), "l"(gptr) : "memory");
}
__device__ __forceinline__ void ldm_x4(uint32_t* r, uint32_t addr) {
  asm volatile("ldmatrix.sync.aligned.m8n8.x4.shared.b16 {%0,%1,%2,%3}, [%4];"
               : "=r"(r[0]), "=r"(r[1]), "=r"(r[2]), "=r"(r[3]) : "r"(addr));
}
__device__ __forceinline__ void mma16816(float* d, const uint32_t* a,
                                         const uint32_t* b) {
  asm volatile(
      "mma.sync.aligned.m16n8k16.row.col.f32.bf16.bf16.f32 "
      "{%0,%1,%2,%3}, {%4,%5,%6,%7}, {%8,%9}, {%0,%1,%2,%3};"
      : "+f"(d[0]), "+f"(d[1]), "+f"(d[2]), "+f"(d[3])
      : "r"(a[0]), "r"(a[1]), "r"(a[2]), "r"(a[3]), "r"(b[0]), "r"(b[1]));
}
__device__ __forceinline__ unsigned long long ffma2(unsigned long long a,
                                                    unsigned long long b,
                                                    unsigned long long c) {
  unsigned long long d;
  asm("fma.rn.f32x2 %0, %1, %2, %3;" : "=l"(d) : "l"(a), "l"(b), "l"(c));
  return d;
}
__device__ __forceinline__ unsigned long long pack2(float lo, float hi) {
  unsigned long long d;
  asm("mov.b64 %0, {%1, %2};" : "=l"(d) : "f"(lo), "f"(hi));
  return d;
}
__device__ __forceinline__ void unpack2(float& lo, float& hi,
                                        unsigned long long v) {
  asm("mov.b64 {%0, %1}, %2;" : "=f"(lo), "=f"(hi) : "l"(v));
}

// ---------------------------------------------------------------------------
// Kernel 1 (fused): radial MLP + SH -> bf16 hi/lo planes [z][256].
// ---------------------------------------------------------------------------
__global__ __launch_bounds__(128, 3) void feat_kernel(
    const float* __restrict__ r,  const float* __restrict__ W1,
    const float* __restrict__ b1, const float* __restrict__ W2,
    const float* __restrict__ b2) {
  extern __shared__ float sm[];
  float* sW1t = sm;                      // [64][68] transposed
  float* sW2  = sm + 4352;               // [64][60]
  float* sb1  = sm + 8192;
  float* sb2  = sm + 8256;
  float* sB   = sm + 8320;               // union: basis [64][128] / staging
  uint32_t* stg = (uint32_t*)sB;         // 2 planes x [128][33] uint32
  const int tid = threadIdx.x;

  #pragma unroll
  for (int i = 0; i < 32; ++i) {
    int idx = tid + i * 128;
    int j = idx >> 6, h = idx & 63;
    sW1t[h * 68 + j] = W1[idx];
  }
  #pragma unroll
  for (int i = 0; i < 30; ++i) sW2[tid + i*128] = W2[tid + i*128];
  if (tid < 64) sb1[tid] = b1[tid];
  if (tid < 60) sb2[tid] = b2[tid];
  __syncthreads();

  const int zb = blockIdx.x * 128;
  const int z = zb + tid;
  const float rx = r[3*z+0], ry = r[3*z+1], rz = r[3*z+2];
  const float rad = sqrtf(rx*rx + ry*ry + rz*rz);
  const float inv = 1.0f / (rad + 1e-12f);
  const float x = rx*inv, y = ry*inv, zc = rz*inv;

  float Y[9];
  Y[0] = 0.28209479177387814f;
  Y[1] = 0.4886025119029199f * y;
  Y[2] = 0.4886025119029199f * zc;
  Y[3] = 0.4886025119029199f * x;
  Y[4] = 1.0925484305920792f * x * y;
  Y[5] = 1.0925484305920792f * y * zc;
  Y[6] = 0.31539156525252005f * (3.0f*zc*zc - 1.0f);
  Y[7] = 1.0925484305920792f * x * zc;
  Y[8] = 0.5462742152960396f * (x*x - y*y);

  {  // radial basis, factorized (3 expf)
    const float DLT = 3.5f / 63.0f;
    int m = (int)floorf(rad / DLT + 0.5f);
    m = (m < 0) ? 0 : ((m > 63) ? 63 : m);
    const float u = rad - DLT * (float)m;
    const float A   = expf(-4.0f * u * u);
    const float tdn = expf(-0.44444444f * u);
    const float tup = expf( 0.44444444f * u);
    const float G1 = 0.98773021f;
    const float W  = 0.97561098f;
    sB[m*128 + tid] = A;
    float P = A, q = tdn * G1;
    for (int j = m - 1; j >= 0; --j) { P *= q; q *= W; sB[j*128 + tid] = P; }
    P = A; q = tup * G1;
    for (int j = m + 1; j < 64; ++j) { P *= q; q *= W; sB[j*128 + tid] = P; }
  }
  __syncthreads();

  unsigned long long Bu[32];
  #pragma unroll
  for (int q = 0; q < 32; ++q)
    Bu[q] = pack2(sB[(2*q)*128 + tid], sB[(2*q+1)*128 + tid]);

  unsigned long long Ru[30];
  #pragma unroll
  for (int q = 0; q < 30; ++q) Ru[q] = pack2(sb2[2*q], sb2[2*q+1]);

  #pragma unroll 4
  for (int h = 0; h < 64; ++h) {
    unsigned long long aA = 0ull, aB = 0ull;
    const float bias = sb1[h];
    #pragma unroll
    for (int q = 0; q < 16; ++q) {
      ulonglong2 w = *(const ulonglong2*)&sW1t[h*68 + q*4];
      aA = ffma2(Bu[2*q],   w.x, aA);
      aB = ffma2(Bu[2*q+1], w.y, aB);
    }
    float f0, f1, f2, f3;
    unpack2(f0, f1, aA);
    unpack2(f2, f3, aB);
    const float a = fmaxf(bias + ((f0 + f1) + (f2 + f3)), 0.0f);
    const unsigned long long ap = pack2(a, a);
    #pragma unroll
    for (int q = 0; q < 15; ++q) {
      ulonglong2 w = *(const ulonglong2*)&sW2[h*60 + q*4];
      Ru[2*q]   = ffma2(ap, w.x, Ru[2*q]);
      Ru[2*q+1] = ffma2(ap, w.y, Ru[2*q+1]);
    }
  }

  float R[NPATH];
  #pragma unroll
  for (int q = 0; q < 30; ++q) unpack2(R[2*q], R[2*q+1], Ru[q]);

  constexpr int LF[15]   = {0,1,2,1,0,1,2,1,2,2,1,2,0,1,2};
  constexpr int GOFF[15] = {0,4,16,36,48,52,64,84,96,116,136,148,168,172,184};
  __nv_bfloat16* stHi = (__nv_bfloat16*)stg;              // [128][66]
  __nv_bfloat16* stLo = (__nv_bfloat16*)(stg + 128*33);

  #pragma unroll
  for (int c = 0; c < 4; ++c) {
    __syncthreads();
    if (c == 3) {
      #pragma unroll
      for (int w = 6; w < 32; ++w) {
        stg[tid*33 + w] = 0u;
        stg[128*33 + tid*33 + w] = 0u;
      }
    }
    #pragma unroll
    for (int p = 0; p < NPATH; ++p) {
      const int l  = LF[p >> 2];
      const int yo = (l == 0) ? 0 : ((l == 1) ? 1 : 4);
      const int kb = GOFF[p >> 2] + (p & 3) * (2*l + 1);
      #pragma unroll
      for (int mm = 0; mm < 2*l + 1; ++mm) {
        const int k = kb + mm;
        if (k >= c*64 && k < c*64 + 64) {
          const int kk = k - c*64;
          float f = R[p] * Y[yo + mm];
          __nv_bfloat16 hi = __float2bfloat16(f);
          __nv_bfloat16 lo = __float2bfloat16(f - __bfloat162float(hi));
          stHi[tid*66 + kk] = hi;
          stLo[tid*66 + kk] = lo;
        }
      }
    }
    __syncthreads();
    #pragma unroll
    for (int it = 0; it < 16; ++it) {
      int i = tid + it * 128;
      int plane = i >> 10;
      int j = i & 1023;
      int row = j >> 3, q = j & 7;
      const uint32_t* src = stg + plane*(128*33) + row*33 + q*4;
      uint4 v; v.x = src[0]; v.y = src[1]; v.z = src[2]; v.w = src[3];
      (plane ? g_Flo4 : g_Fhi4)[(size_t)(zb + row) * 32 + c*8 + q] = v;
    }
  }
}

// ---------------------------------------------------------------------------
// Kernel 2: pack B = cg^T, segments {hi, lo, hi} at offsets 0/208/416
// ---------------------------------------------------------------------------
__global__ void prepB_kernel(const float* __restrict__ cg) {
  const int n = blockIdx.x;
  for (int kp = threadIdx.x; kp < KP2; kp += blockDim.x) {
    const int seg = kp / SEGP;
    const int k = kp - seg * SEGP;
    float v = (n < NOUT && k < KTOT) ? cg[k * NOUT + n] : 0.0f;
    __nv_bfloat16 hi = __float2bfloat16(v);
    __nv_bfloat16 lo = __float2bfloat16(v - __bfloat162float(hi));
    g_B[n * KP2 + kp] = (seg == 1) ? lo : hi;
  }
}

// ---------------------------------------------------------------------------
// Kernel 3 (templated): mma.sync bf16 GEMM, K'=624, 13 chunks of k48,
// 3-stage cp.async ring, 112B rows. Warp grid 4m x NWN n; warp tile
// 32 x (BC/NWN). Instantiations: <128,4> (512 thr) and <80,5> (640 thr).
// No runtime branches in the hot loop.
// ---------------------------------------------------------------------------
template <int BC, int NWN>
__global__ void __launch_bounds__(128 * NWN)
mma_kernel(float* __restrict__ out, int jb0) {
  constexpr int THREADS = 128 * NWN;
  constexpr int TN   = BC / NWN;       // warp n-tile (32 or 16)
  constexpr int NT16 = TN / 16;
  constexpr int NT8  = TN / 8;
  constexpr int BBUF = BC * 112;

  extern __shared__ char smem[];
  const uint32_t sb = smem_u32(smem);
  const int tid = threadIdx.x;
  const int w = tid >> 5, lane = tid & 31;
  const int wm = w / NWN, wn = w % NWN;
  const int jb = jb0 + blockIdx.x * BC;
  const int zb = blockIdx.y * 128;

  auto issue = [&](int c, int buf) {
    const uint32_t base = sb + buf * (ABUF + BBUF);
    const char* Bb = (const char*)g_B;
    #pragma unroll
    for (int i = tid; i < (128 + BC) * 6; i += THREADS) {
      int half = i >= 768;                     // 0: A (128 rows), 1: B (BC rows)
      int j = i - half * 768;
      int row = j / 6, quad = j - row * 6;
      int kp = c * CH + quad * 8;
      uint32_t dst = base + half * ABUF + row * 112 + quad * 16;
      if (half) {
        cp16(dst, Bb + (size_t)(jb + row) * (KP2*2) + kp * 2);
      } else {
        int seg = (kp >= 2*SEGP) ? 2 : (kp >= SEGP ? 1 : 0);
        int kk = kp - seg * SEGP;
        const char* Asrc = (const char*)(seg == 2 ? g_Flo4 : g_Fhi4)
                           + (size_t)(zb + row) * 512 + kk * 2;
        cp16(dst, Asrc);
      }
    }
    asm volatile("cp.async.commit_group;" ::: "memory");
  };

  float acc[2][NT8][4];
  #pragma unroll
  for (int mt = 0; mt < 2; ++mt)
    #pragma unroll
    for (int nt = 0; nt < NT8; ++nt)
      #pragma unroll
      for (int q = 0; q < 4; ++q) acc[mt][nt][q] = 0.0f;

  issue(0, 0);
  issue(1, 1);

  for (int c = 0; c < NCH; ++c) {
    if (c >= NCH - 2)
      asm volatile("cp.async.wait_group 0;" ::: "memory");
    else
      asm volatile("cp.async.wait_group 1;" ::: "memory");
    __syncthreads();

    if (c + 2 < NCH) issue(c + 2, (c + 2) % STGN);

    const uint32_t aBase = sb + (c % STGN) * (ABUF + BBUF);
    const uint32_t bBase = aBase + ABUF;

    #pragma unroll
    for (int ks = 0; ks < 3; ++ks) {
      uint32_t afr[2][4];
      #pragma unroll
      for (int mt = 0; mt < 2; ++mt) {
        uint32_t addr = aBase + (wm*32 + mt*16 + (lane & 15)) * 112
                      + ks*32 + (lane >> 4) * 16;
        ldm_x4(afr[mt], addr);
      }
      uint32_t bfr[NT16 * 4];
      #pragma unroll
      for (int nt = 0; nt < NT16; ++nt) {
        uint32_t addr = bBase
            + (wn*TN + nt*16 + ((lane >> 4) << 3) + (lane & 7)) * 112
            + ks*32 + ((lane >> 3) & 1) * 16;
        ldm_x4(&bfr[nt * 4], addr);
      }
      #pragma unroll
      for (int mt = 0; mt < 2; ++mt)
        #pragma unroll
        for (int nt = 0; nt < NT8; ++nt)
          mma16816(acc[mt][nt], afr[mt], &bfr[nt * 2]);
    }
  }

  // epilogue
  const int r0 = lane >> 2;
  const int c2 = (lane & 3) * 2;
  #pragma unroll
  for (int mt = 0; mt < 2; ++mt) {
    #pragma unroll
    for (int nt = 0; nt < NT8; ++nt) {
      const int col = jb + wn*TN + nt*8 + c2;
      if (col < NOUT) {
        const int zr = zb + wm*32 + mt*16 + r0;
        *(float2*)&out[(size_t)zr * NOUT + col] =
            make_float2(acc[mt][nt][0], acc[mt][nt][1]);
        *(float2*)&out[(size_t)(zr + 8) * NOUT + col] =
            make_float2(acc[mt][nt][2], acc[mt][nt][3]);
      }
    }
  }
}

// ---------------------------------------------------------------------------
extern "C" void kernel_launch(void* const* d_in, const int* in_sizes, int n_in,
                              void* d_out, int out_size) {
  const float* r  = (const float*)d_in[0];
  const float* W1 = (const float*)d_in[1];
  const float* b1 = (const float*)d_in[2];
  const float* W2 = (const float*)d_in[3];
  const float* b2 = (const float*)d_in[4];
  const float* cg = (const float*)d_in[5];
  float* out = (float*)d_out;

  const int smem1 = (4352 + 3840 + 128 + 8448) * 4;       // 67072 B
  const int smemM = STGN * (ABUF + 128 * 112);            // 86016 B
  const int smemN = STGN * (ABUF + 80 * 112);             // 69888 B
  cudaFuncSetAttribute(feat_kernel,
      cudaFuncAttributeMaxDynamicSharedMemorySize, smem1);
  cudaFuncSetAttribute(mma_kernel<128, 4>,
      cudaFuncAttributeMaxDynamicSharedMemorySize, smemM);
  cudaFuncSetAttribute(mma_kernel<80, 5>,
      cudaFuncAttributeMaxDynamicSharedMemorySize, smemN);

  feat_kernel<<<ZTOT/128, 128, smem1>>>(r, W1, b1, W2, b2);
  prepB_kernel<<<NBP, 224>>>(cg);
  mma_kernel<128, 4><<<dim3(2, ZTOT/128), 512, smemM>>>(out, 0);
  mma_kernel<80, 5><<<dim3(1, ZTOT/128), 640, smemN>>>(out, 256);
}

// round 13
// speedup vs baseline: 1.2766x; 1.0229x over previous
#include <cuda_runtime.h>
#include <cuda_bf16.h>
#include <math.h>
#include <stdint.h>

#define ZTOT  65536
#define KTOT  204
#define NPATH 60
#define NOUT  324
#define SEGP  208            // per-segment padding (204 + 4)
#define KP2   624            // K' = 3 * 208
#define CH    48             // k' per chunk
#define NCH   13             // 624 / 48
#define NBP   384
#define STGN  3
#define ABUF  14336          // 128 * 112

// ---------------- scratch ----------------
__device__ uint4 g_Fhi4[(size_t)ZTOT * 32];           // [z][256] bf16 hi plane
__device__ uint4 g_Flo4[(size_t)ZTOT * 32];           // [z][256] bf16 lo plane
__device__ __align__(16) __nv_bfloat16 g_B[NBP * KP2];

// ---------------- helpers ----------------
__device__ __forceinline__ uint32_t smem_u32(const void* p) {
  uint32_t a;
  asm("{ .reg .u64 t; cvta.to.shared.u64 t, %1; cvt.u32.u64 %0, t; }"
      : "=r"(a) : "l"(p));
  return a;
}
__device__ __forceinline__ void cp16(uint32_t smaddr, const void* gptr) {
  asm volatile("cp.async.cg.shared.global [%0], [%1], 16;"
               :: "r"(smaddr), "l"(gptr) : "memory");
}
__device__ __forceinline__ void ldm_x4(uint32_t* r, uint32_t addr) {
  asm volatile("ldmatrix.sync.aligned.m8n8.x4.shared.b16 {%0,%1,%2,%3}, [%4];"
               : "=r"(r[0]), "=r"(r[1]), "=r"(r[2]), "=r"(r[3]) : "r"(addr));
}
__device__ __forceinline__ void mma16816(float* d, const uint32_t* a,
                                         const uint32_t* b) {
  asm volatile(
      "mma.sync.aligned.m16n8k16.row.col.f32.bf16.bf16.f32 "
      "{%0,%1,%2,%3}, {%4,%5,%6,%7}, {%8,%9}, {%0,%1,%2,%3};"
      : "+f"(d[0]), "+f"(d[1]), "+f"(d[2]), "+f"(d[3])
      : "r"(a[0]), "r"(a[1]), "r"(a[2]), "r"(a[3]), "r"(b[0]), "r"(b[1]));
}
__device__ __forceinline__ unsigned long long ffma2(unsigned long long a,
                                                    unsigned long long b,
                                                    unsigned long long c) {
  unsigned long long d;
  asm("fma.rn.f32x2 %0, %1, %2, %3;" : "=l"(d) : "l"(a), "l"(b), "l"(c));
  return d;
}
__device__ __forceinline__ unsigned long long pack2(float lo, float hi) {
  unsigned long long d;
  asm("mov.b64 %0, {%1, %2};" : "=l"(d) : "f"(lo), "f"(hi));
  return d;
}
__device__ __forceinline__ void unpack2(float& lo, float& hi,
                                        unsigned long long v) {
  asm("mov.b64 {%0, %1}, %2;" : "=f"(lo), "=f"(hi) : "l"(v));
}

// ---------------------------------------------------------------------------
// Kernel 1 (fused): radial MLP + SH -> bf16 hi/lo planes [z][256].
// ---------------------------------------------------------------------------
__global__ __launch_bounds__(128, 3) void feat_kernel(
    const float* __restrict__ r,  const float* __restrict__ W1,
    const float* __restrict__ b1, const float* __restrict__ W2,
    const float* __restrict__ b2) {
  extern __shared__ float sm[];
  float* sW1t = sm;                      // [64][68] transposed
  float* sW2  = sm + 4352;               // [64][60]
  float* sb1  = sm + 8192;
  float* sb2  = sm + 8256;
  float* sB   = sm + 8320;               // union: basis [64][128] / staging
  uint32_t* stg = (uint32_t*)sB;         // 2 planes x [128][33] uint32
  const int tid = threadIdx.x;

  #pragma unroll
  for (int i = 0; i < 32; ++i) {
    int idx = tid + i * 128;
    int j = idx >> 6, h = idx & 63;
    sW1t[h * 68 + j] = W1[idx];
  }
  #pragma unroll
  for (int i = 0; i < 30; ++i) sW2[tid + i*128] = W2[tid + i*128];
  if (tid < 64) sb1[tid] = b1[tid];
  if (tid < 60) sb2[tid] = b2[tid];
  __syncthreads();

  const int zb = blockIdx.x * 128;
  const int z = zb + tid;
  const float rx = r[3*z+0], ry = r[3*z+1], rz = r[3*z+2];
  const float rad = sqrtf(rx*rx + ry*ry + rz*rz);
  const float inv = 1.0f / (rad + 1e-12f);
  const float x = rx*inv, y = ry*inv, zc = rz*inv;

  float Y[9];
  Y[0] = 0.28209479177387814f;
  Y[1] = 0.4886025119029199f * y;
  Y[2] = 0.4886025119029199f * zc;
  Y[3] = 0.4886025119029199f * x;
  Y[4] = 1.0925484305920792f * x * y;
  Y[5] = 1.0925484305920792f * y * zc;
  Y[6] = 0.31539156525252005f * (3.0f*zc*zc - 1.0f);
  Y[7] = 1.0925484305920792f * x * zc;
  Y[8] = 0.5462742152960396f * (x*x - y*y);

  {  // radial basis, factorized (3 expf)
    const float DLT = 3.5f / 63.0f;
    int m = (int)floorf(rad / DLT + 0.5f);
    m = (m < 0) ? 0 : ((m > 63) ? 63 : m);
    const float u = rad - DLT * (float)m;
    const float A   = expf(-4.0f * u * u);
    const float tdn = expf(-0.44444444f * u);
    const float tup = expf( 0.44444444f * u);
    const float G1 = 0.98773021f;
    const float W  = 0.97561098f;
    sB[m*128 + tid] = A;
    float P = A, q = tdn * G1;
    for (int j = m - 1; j >= 0; --j) { P *= q; q *= W; sB[j*128 + tid] = P; }
    P = A; q = tup * G1;
    for (int j = m + 1; j < 64; ++j) { P *= q; q *= W; sB[j*128 + tid] = P; }
  }
  __syncthreads();

  unsigned long long Bu[32];
  #pragma unroll
  for (int q = 0; q < 32; ++q)
    Bu[q] = pack2(sB[(2*q)*128 + tid], sB[(2*q+1)*128 + tid]);

  unsigned long long Ru[30];
  #pragma unroll
  for (int q = 0; q < 30; ++q) Ru[q] = pack2(sb2[2*q], sb2[2*q+1]);

  #pragma unroll 4
  for (int h = 0; h < 64; ++h) {
    unsigned long long aA = 0ull, aB = 0ull;
    const float bias = sb1[h];
    #pragma unroll
    for (int q = 0; q < 16; ++q) {
      ulonglong2 w = *(const ulonglong2*)&sW1t[h*68 + q*4];
      aA = ffma2(Bu[2*q],   w.x, aA);
      aB = ffma2(Bu[2*q+1], w.y, aB);
    }
    float f0, f1, f2, f3;
    unpack2(f0, f1, aA);
    unpack2(f2, f3, aB);
    const float a = fmaxf(bias + ((f0 + f1) + (f2 + f3)), 0.0f);
    const unsigned long long ap = pack2(a, a);
    #pragma unroll
    for (int q = 0; q < 15; ++q) {
      ulonglong2 w = *(const ulonglong2*)&sW2[h*60 + q*4];
      Ru[2*q]   = ffma2(ap, w.x, Ru[2*q]);
      Ru[2*q+1] = ffma2(ap, w.y, Ru[2*q+1]);
    }
  }

  float R[NPATH];
  #pragma unroll
  for (int q = 0; q < 30; ++q) unpack2(R[2*q], R[2*q+1], Ru[q]);

  constexpr int LF[15]   = {0,1,2,1,0,1,2,1,2,2,1,2,0,1,2};
  constexpr int GOFF[15] = {0,4,16,36,48,52,64,84,96,116,136,148,168,172,184};
  __nv_bfloat16* stHi = (__nv_bfloat16*)stg;              // [128][66]
  __nv_bfloat16* stLo = (__nv_bfloat16*)(stg + 128*33);

  #pragma unroll
  for (int c = 0; c < 4; ++c) {
    __syncthreads();
    if (c == 3) {
      #pragma unroll
      for (int w = 6; w < 32; ++w) {
        stg[tid*33 + w] = 0u;
        stg[128*33 + tid*33 + w] = 0u;
      }
    }
    #pragma unroll
    for (int p = 0; p < NPATH; ++p) {
      const int l  = LF[p >> 2];
      const int yo = (l == 0) ? 0 : ((l == 1) ? 1 : 4);
      const int kb = GOFF[p >> 2] + (p & 3) * (2*l + 1);
      #pragma unroll
      for (int mm = 0; mm < 2*l + 1; ++mm) {
        const int k = kb + mm;
        if (k >= c*64 && k < c*64 + 64) {
          const int kk = k - c*64;
          float f = R[p] * Y[yo + mm];
          __nv_bfloat16 hi = __float2bfloat16(f);
          __nv_bfloat16 lo = __float2bfloat16(f - __bfloat162float(hi));
          stHi[tid*66 + kk] = hi;
          stLo[tid*66 + kk] = lo;
        }
      }
    }
    __syncthreads();
    #pragma unroll
    for (int it = 0; it < 16; ++it) {
      int i = tid + it * 128;
      int plane = i >> 10;
      int j = i & 1023;
      int row = j >> 3, q = j & 7;
      const uint32_t* src = stg + plane*(128*33) + row*33 + q*4;
      uint4 v; v.x = src[0]; v.y = src[1]; v.z = src[2]; v.w = src[3];
      (plane ? g_Flo4 : g_Fhi4)[(size_t)(zb + row) * 32 + c*8 + q] = v;
    }
  }
}

// ---------------------------------------------------------------------------
// Kernel 2: pack B = cg^T, segments {hi, lo, hi} at offsets 0/208/416
// ---------------------------------------------------------------------------
__global__ void prepB_kernel(const float* __restrict__ cg) {
  const int n = blockIdx.x;
  for (int kp = threadIdx.x; kp < KP2; kp += blockDim.x) {
    const int seg = kp / SEGP;
    const int k = kp - seg * SEGP;
    float v = (n < NOUT && k < KTOT) ? cg[k * NOUT + n] : 0.0f;
    __nv_bfloat16 hi = __float2bfloat16(v);
    __nv_bfloat16 lo = __float2bfloat16(v - __bfloat162float(hi));
    g_B[n * KP2 + kp] = (seg == 1) ? lo : hi;
  }
}

// ---------------------------------------------------------------------------
// Kernel 3 (templated): mma.sync bf16 GEMM, K'=624, 13 chunks of k48,
// 3-stage cp.async ring, 112B rows. Warp grid 2m x WN n; warp tile 64x32.
// Instantiations: <128,4> (256 thr, cols 0-256), <96,3> (192 thr, 256-352).
// ---------------------------------------------------------------------------
template <int BC, int WN>
__global__ void __launch_bounds__(64 * WN)
mma_kernel(float* __restrict__ out, int jb0) {
  constexpr int THREADS = 64 * WN;
  constexpr int BBUF = BC * 112;
  constexpr int TOT  = (128 + BC) * 6;     // cp16 ops per chunk

  extern __shared__ char smem[];
  const uint32_t sb = smem_u32(smem);
  const int tid = threadIdx.x;
  const int w = tid >> 5, lane = tid & 31;
  const int wm = w / WN, wn = w % WN;      // 2 x WN warp grid
  const int jb = jb0 + blockIdx.x * BC;
  const int zb = blockIdx.y * 128;

  auto issue = [&](int c, int buf) {
    const uint32_t base = sb + buf * (ABUF + BBUF);
    const char* Bb = (const char*)g_B;
    #pragma unroll
    for (int it = 0; it < (TOT + THREADS - 1) / THREADS; ++it) {
      int i = tid + it * THREADS;
      if ((TOT % THREADS == 0) || i < TOT) {
        int half = i >= 768;                 // 0: A (128 rows), 1: B (BC rows)
        int j = i - half * 768;
        int row = j / 6, quad = j - row * 6;
        int kp = c * CH + quad * 8;
        uint32_t dst = base + half * ABUF + row * 112 + quad * 16;
        if (half) {
          cp16(dst, Bb + (size_t)(jb + row) * (KP2*2) + kp * 2);
        } else {
          int seg = (kp >= 2*SEGP) ? 2 : (kp >= SEGP ? 1 : 0);
          int kk = kp - seg * SEGP;
          const char* Asrc = (const char*)(seg == 2 ? g_Flo4 : g_Fhi4)
                             + (size_t)(zb + row) * 512 + kk * 2;
          cp16(dst, Asrc);
        }
      }
    }
    asm volatile("cp.async.commit_group;" ::: "memory");
  };

  float acc[4][4][4];
  #pragma unroll
  for (int mt = 0; mt < 4; ++mt)
    #pragma unroll
    for (int nt = 0; nt < 4; ++nt)
      #pragma unroll
      for (int q = 0; q < 4; ++q) acc[mt][nt][q] = 0.0f;

  issue(0, 0);
  issue(1, 1);

  for (int c = 0; c < NCH; ++c) {
    if (c >= NCH - 2)
      asm volatile("cp.async.wait_group 0;" ::: "memory");
    else
      asm volatile("cp.async.wait_group 1;" ::: "memory");
    __syncthreads();

    if (c + 2 < NCH) issue(c + 2, (c + 2) % STGN);

    const uint32_t aBase = sb + (c % STGN) * (ABUF + BBUF);
    const uint32_t bBase = aBase + ABUF;

    #pragma unroll
    for (int ks = 0; ks < 3; ++ks) {
      uint32_t afr[4][4];
      #pragma unroll
      for (int mt = 0; mt < 4; ++mt) {
        uint32_t addr = aBase + (wm*64 + mt*16 + (lane & 15)) * 112
                      + ks*32 + (lane >> 4) * 16;
        ldm_x4(afr[mt], addr);
      }
      uint32_t bfr[8];
      #pragma unroll
      for (int nt = 0; nt < 2; ++nt) {
        uint32_t addr = bBase
            + (wn*32 + nt*16 + ((lane >> 4) << 3) + (lane & 7)) * 112
            + ks*32 + ((lane >> 3) & 1) * 16;
        ldm_x4(&bfr[nt * 4], addr);
      }
      #pragma unroll
      for (int mt = 0; mt < 4; ++mt)
        #pragma unroll
        for (int nt = 0; nt < 4; ++nt)
          mma16816(acc[mt][nt], afr[mt], &bfr[nt * 2]);
    }
  }

  // epilogue
  const int r0 = lane >> 2;
  const int c2 = (lane & 3) * 2;
  #pragma unroll
  for (int mt = 0; mt < 4; ++mt) {
    #pragma unroll
    for (int nt = 0; nt < 4; ++nt) {
      const int col = jb + wn*32 + nt*8 + c2;
      if (col < NOUT) {
        const int zr = zb + wm*64 + mt*16 + r0;
        *(float2*)&out[(size_t)zr * NOUT + col] =
            make_float2(acc[mt][nt][0], acc[mt][nt][1]);
        *(float2*)&out[(size_t)(zr + 8) * NOUT + col] =
            make_float2(acc[mt][nt][2], acc[mt][nt][3]);
      }
    }
  }
}

// ---------------------------------------------------------------------------
extern "C" void kernel_launch(void* const* d_in, const int* in_sizes, int n_in,
                              void* d_out, int out_size) {
  const float* r  = (const float*)d_in[0];
  const float* W1 = (const float*)d_in[1];
  const float* b1 = (const float*)d_in[2];
  const float* W2 = (const float*)d_in[3];
  const float* b2 = (const float*)d_in[4];
  const float* cg = (const float*)d_in[5];
  float* out = (float*)d_out;

  const int smem1 = (4352 + 3840 + 128 + 8448) * 4;       // 67072 B
  const int smemM = STGN * (ABUF + 128 * 112);            // 86016 B
  const int smemN = STGN * (ABUF + 96 * 112);             // 75264 B
  cudaFuncSetAttribute(feat_kernel,
      cudaFuncAttributeMaxDynamicSharedMemorySize, smem1);
  cudaFuncSetAttribute(mma_kernel<128, 4>,
      cudaFuncAttributeMaxDynamicSharedMemorySize, smemM);
  cudaFuncSetAttribute(mma_kernel<96, 3>,
      cudaFuncAttributeMaxDynamicSharedMemorySize, smemN);

  feat_kernel<<<ZTOT/128, 128, smem1>>>(r, W1, b1, W2, b2);
  prepB_kernel<<<NBP, 224>>>(cg);
  mma_kernel<128, 4><<<dim3(2, ZTOT/128), 256, smemM>>>(out, 0);
  mma_kernel<96, 3><<<dim3(1, ZTOT/128), 192, smemN>>>(out, 256);
}

// round 14
// speedup vs baseline: 1.3578x; 1.0636x over previous
#include <cuda_runtime.h>
#include <cuda_bf16.h>
#include <math.h>
#include <stdint.h>

#define ZTOT  65536
#define KTOT  204
#define NPATH 60
#define NOUT  324
#define SEGP  208            // per-segment padding (204 + 4)
#define KP2   624            // K' = 3 * 208
#define CH    48             // k' per chunk
#define NCH   13             // 624 / 48
#define NBP   384
#define STGN  3
#define ABUF  14336          // 128 * 112

// ---------------- scratch ----------------
__device__ uint4 g_Fhi4[(size_t)ZTOT * 32];           // [z][256] bf16 hi plane
__device__ uint4 g_Flo4[(size_t)ZTOT * 32];           // [z][256] bf16 lo plane
__device__ __align__(16) __nv_bfloat16 g_B[NBP * KP2];

// ---------------- helpers ----------------
__device__ __forceinline__ uint32_t smem_u32(const void* p) {
  uint32_t a;
  asm("{ .reg .u64 t; cvta.to.shared.u64 t, %1; cvt.u32.u64 %0, t; }"
      : "=r"(a) : "l"(p));
  return a;
}
__device__ __forceinline__ void cp16(uint32_t smaddr, const void* gptr) {
  asm volatile("cp.async.cg.shared.global [%0], [%1], 16;"
               :: "r"(smaddr), "l"(gptr) : "memory");
}
__device__ __forceinline__ void ldm_x4(uint32_t* r, uint32_t addr) {
  asm volatile("ldmatrix.sync.aligned.m8n8.x4.shared.b16 {%0,%1,%2,%3}, [%4];"
               : "=r"(r[0]), "=r"(r[1]), "=r"(r[2]), "=r"(r[3]) : "r"(addr));
}
__device__ __forceinline__ void mma16816(float* d, const uint32_t* a,
                                         const uint32_t* b) {
  asm volatile(
      "mma.sync.aligned.m16n8k16.row.col.f32.bf16.bf16.f32 "
      "{%0,%1,%2,%3}, {%4,%5,%6,%7}, {%8,%9}, {%0,%1,%2,%3};"
      : "+f"(d[0]), "+f"(d[1]), "+f"(d[2]), "+f"(d[3])
      : "r"(a[0]), "r"(a[1]), "r"(a[2]), "r"(a[3]), "r"(b[0]), "r"(b[1]));
}
__device__ __forceinline__ unsigned long long ffma2(unsigned long long a,
                                                    unsigned long long b,
                                                    unsigned long long c) {
  unsigned long long d;
  asm("fma.rn.f32x2 %0, %1, %2, %3;" : "=l"(d) : "l"(a), "l"(b), "l"(c));
  return d;
}
__device__ __forceinline__ unsigned long long pack2(float lo, float hi) {
  unsigned long long d;
  asm("mov.b64 %0, {%1, %2};" : "=l"(d) : "f"(lo), "f"(hi));
  return d;
}
__device__ __forceinline__ void unpack2(float& lo, float& hi,
                                        unsigned long long v) {
  asm("mov.b64 {%0, %1}, %2;" : "=f"(lo), "=f"(hi) : "l"(v));
}

// ---------------------------------------------------------------------------
// Kernel 1 (fused): radial MLP + SH -> bf16 hi/lo planes [z][256].
// ---------------------------------------------------------------------------
__global__ __launch_bounds__(128, 3) void feat_kernel(
    const float* __restrict__ r,  const float* __restrict__ W1,
    const float* __restrict__ b1, const float* __restrict__ W2,
    const float* __restrict__ b2) {
  extern __shared__ float sm[];
  float* sW1t = sm;                      // [64][68] transposed
  float* sW2  = sm + 4352;               // [64][60]
  float* sb1  = sm + 8192;
  float* sb2  = sm + 8256;
  float* sB   = sm + 8320;               // union: basis [64][128] / staging
  uint32_t* stg = (uint32_t*)sB;         // 2 planes x [128][33] uint32
  const int tid = threadIdx.x;

  #pragma unroll
  for (int i = 0; i < 32; ++i) {
    int idx = tid + i * 128;
    int j = idx >> 6, h = idx & 63;
    sW1t[h * 68 + j] = W1[idx];
  }
  #pragma unroll
  for (int i = 0; i < 30; ++i) sW2[tid + i*128] = W2[tid + i*128];
  if (tid < 64) sb1[tid] = b1[tid];
  if (tid < 60) sb2[tid] = b2[tid];
  __syncthreads();

  const int zb = blockIdx.x * 128;
  const int z = zb + tid;
  const float rx = r[3*z+0], ry = r[3*z+1], rz = r[3*z+2];
  const float rad = sqrtf(rx*rx + ry*ry + rz*rz);
  const float inv = 1.0f / (rad + 1e-12f);
  const float x = rx*inv, y = ry*inv, zc = rz*inv;

  float Y[9];
  Y[0] = 0.28209479177387814f;
  Y[1] = 0.4886025119029199f * y;
  Y[2] = 0.4886025119029199f * zc;
  Y[3] = 0.4886025119029199f * x;
  Y[4] = 1.0925484305920792f * x * y;
  Y[5] = 1.0925484305920792f * y * zc;
  Y[6] = 0.31539156525252005f * (3.0f*zc*zc - 1.0f);
  Y[7] = 1.0925484305920792f * x * zc;
  Y[8] = 0.5462742152960396f * (x*x - y*y);

  {  // radial basis, factorized (3 expf)
    const float DLT = 3.5f / 63.0f;
    int m = (int)floorf(rad / DLT + 0.5f);
    m = (m < 0) ? 0 : ((m > 63) ? 63 : m);
    const float u = rad - DLT * (float)m;
    const float A   = expf(-4.0f * u * u);
    const float tdn = expf(-0.44444444f * u);
    const float tup = expf( 0.44444444f * u);
    const float G1 = 0.98773021f;
    const float W  = 0.97561098f;
    sB[m*128 + tid] = A;
    float P = A, q = tdn * G1;
    for (int j = m - 1; j >= 0; --j) { P *= q; q *= W; sB[j*128 + tid] = P; }
    P = A; q = tup * G1;
    for (int j = m + 1; j < 64; ++j) { P *= q; q *= W; sB[j*128 + tid] = P; }
  }
  __syncthreads();

  unsigned long long Bu[32];
  #pragma unroll
  for (int q = 0; q < 32; ++q)
    Bu[q] = pack2(sB[(2*q)*128 + tid], sB[(2*q+1)*128 + tid]);

  unsigned long long Ru[30];
  #pragma unroll
  for (int q = 0; q < 30; ++q) Ru[q] = pack2(sb2[2*q], sb2[2*q+1]);

  #pragma unroll 4
  for (int h = 0; h < 64; ++h) {
    unsigned long long aA = 0ull, aB = 0ull;
    const float bias = sb1[h];
    #pragma unroll
    for (int q = 0; q < 16; ++q) {
      ulonglong2 w = *(const ulonglong2*)&sW1t[h*68 + q*4];
      aA = ffma2(Bu[2*q],   w.x, aA);
      aB = ffma2(Bu[2*q+1], w.y, aB);
    }
    float f0, f1, f2, f3;
    unpack2(f0, f1, aA);
    unpack2(f2, f3, aB);
    const float a = fmaxf(bias + ((f0 + f1) + (f2 + f3)), 0.0f);
    const unsigned long long ap = pack2(a, a);
    #pragma unroll
    for (int q = 0; q < 15; ++q) {
      ulonglong2 w = *(const ulonglong2*)&sW2[h*60 + q*4];
      Ru[2*q]   = ffma2(ap, w.x, Ru[2*q]);
      Ru[2*q+1] = ffma2(ap, w.y, Ru[2*q+1]);
    }
  }

  float R[NPATH];
  #pragma unroll
  for (int q = 0; q < 30; ++q) unpack2(R[2*q], R[2*q+1], Ru[q]);

  constexpr int LF[15]   = {0,1,2,1,0,1,2,1,2,2,1,2,0,1,2};
  constexpr int GOFF[15] = {0,4,16,36,48,52,64,84,96,116,136,148,168,172,184};
  __nv_bfloat16* stHi = (__nv_bfloat16*)stg;              // [128][66]
  __nv_bfloat16* stLo = (__nv_bfloat16*)(stg + 128*33);

  #pragma unroll
  for (int c = 0; c < 4; ++c) {
    __syncthreads();
    if (c == 3) {
      #pragma unroll
      for (int w = 6; w < 32; ++w) {
        stg[tid*33 + w] = 0u;
        stg[128*33 + tid*33 + w] = 0u;
      }
    }
    #pragma unroll
    for (int p = 0; p < NPATH; ++p) {
      const int l  = LF[p >> 2];
      const int yo = (l == 0) ? 0 : ((l == 1) ? 1 : 4);
      const int kb = GOFF[p >> 2] + (p & 3) * (2*l + 1);
      #pragma unroll
      for (int mm = 0; mm < 2*l + 1; ++mm) {
        const int k = kb + mm;
        if (k >= c*64 && k < c*64 + 64) {
          const int kk = k - c*64;
          float f = R[p] * Y[yo + mm];
          __nv_bfloat16 hi = __float2bfloat16(f);
          __nv_bfloat16 lo = __float2bfloat16(f - __bfloat162float(hi));
          stHi[tid*66 + kk] = hi;
          stLo[tid*66 + kk] = lo;
        }
      }
    }
    __syncthreads();
    #pragma unroll
    for (int it = 0; it < 16; ++it) {
      int i = tid + it * 128;
      int plane = i >> 10;
      int j = i & 1023;
      int row = j >> 3, q = j & 7;
      const uint32_t* src = stg + plane*(128*33) + row*33 + q*4;
      uint4 v; v.x = src[0]; v.y = src[1]; v.z = src[2]; v.w = src[3];
      (plane ? g_Flo4 : g_Fhi4)[(size_t)(zb + row) * 32 + c*8 + q] = v;
    }
  }
}

// ---------------------------------------------------------------------------
// Kernel 2: pack B = cg^T, segments {hi, lo, hi} at offsets 0/208/416
// ---------------------------------------------------------------------------
__global__ void prepB_kernel(const float* __restrict__ cg) {
  const int n = blockIdx.x;
  for (int kp = threadIdx.x; kp < KP2; kp += blockDim.x) {
    const int seg = kp / SEGP;
    const int k = kp - seg * SEGP;
    float v = (n < NOUT && k < KTOT) ? cg[k * NOUT + n] : 0.0f;
    __nv_bfloat16 hi = __float2bfloat16(v);
    __nv_bfloat16 lo = __float2bfloat16(v - __bfloat162float(hi));
    g_B[n * KP2 + kp] = (seg == 1) ? lo : hi;
  }
}

// ---------------------------------------------------------------------------
// Kernel 3: merged GEMM. One launch, grid (3, Z/128), 256 threads.
// bx 0,1 -> BC=128, warp grid 2x4 (tile 64x32); bx 2 -> BC=96, warp grid
// 4x2 (tile 32x48). Same-zb tiles run adjacently -> A reused in L2.
// ---------------------------------------------------------------------------
template <int BC, int NWM, int NWN>
__device__ __forceinline__ void mma_body(float* __restrict__ out, int jb,
                                         int zb, char* smem) {
  constexpr int TM   = 128 / NWM;
  constexpr int TN   = BC / NWN;
  constexpr int MT   = TM / 16;
  constexpr int NT16 = TN / 16;
  constexpr int NT8  = TN / 8;
  constexpr int BBUF = BC * 112;
  constexpr int TOT  = (128 + BC) * 6;

  const uint32_t sb = smem_u32(smem);
  const int tid = threadIdx.x;
  const int w = tid >> 5, lane = tid & 31;
  const int wm = w / NWN, wn = w % NWN;

  auto issue = [&](int c, int buf) {
    const uint32_t base = sb + buf * (ABUF + BBUF);
    const char* Bb = (const char*)g_B;
    #pragma unroll
    for (int it = 0; it < (TOT + 255) / 256; ++it) {
      int i = tid + it * 256;
      if ((TOT % 256 == 0) || i < TOT) {
        int half = i >= 768;                 // 0: A (128 rows), 1: B (BC rows)
        int j = i - half * 768;
        int row = j / 6, quad = j - row * 6;
        int kp = c * CH + quad * 8;
        uint32_t dst = base + half * ABUF + row * 112 + quad * 16;
        if (half) {
          cp16(dst, Bb + (size_t)(jb + row) * (KP2*2) + kp * 2);
        } else {
          int seg = (kp >= 2*SEGP) ? 2 : (kp >= SEGP ? 1 : 0);
          int kk = kp - seg * SEGP;
          const char* Asrc = (const char*)(seg == 2 ? g_Flo4 : g_Fhi4)
                             + (size_t)(zb + row) * 512 + kk * 2;
          cp16(dst, Asrc);
        }
      }
    }
    asm volatile("cp.async.commit_group;" ::: "memory");
  };

  float acc[MT][NT8][4];
  #pragma unroll
  for (int mt = 0; mt < MT; ++mt)
    #pragma unroll
    for (int nt = 0; nt < NT8; ++nt)
      #pragma unroll
      for (int q = 0; q < 4; ++q) acc[mt][nt][q] = 0.0f;

  issue(0, 0);
  issue(1, 1);

  for (int c = 0; c < NCH; ++c) {
    if (c >= NCH - 2)
      asm volatile("cp.async.wait_group 0;" ::: "memory");
    else
      asm volatile("cp.async.wait_group 1;" ::: "memory");
    __syncthreads();

    if (c + 2 < NCH) issue(c + 2, (c + 2) % STGN);

    const uint32_t aBase = sb + (c % STGN) * (ABUF + BBUF);
    const uint32_t bBase = aBase + ABUF;

    #pragma unroll
    for (int ks = 0; ks < 3; ++ks) {
      uint32_t afr[MT][4];
      #pragma unroll
      for (int mt = 0; mt < MT; ++mt) {
        uint32_t addr = aBase + (wm*TM + mt*16 + (lane & 15)) * 112
                      + ks*32 + (lane >> 4) * 16;
        ldm_x4(afr[mt], addr);
      }
      uint32_t bfr[NT16 * 4];
      #pragma unroll
      for (int nt = 0; nt < NT16; ++nt) {
        uint32_t addr = bBase
            + (wn*TN + nt*16 + ((lane >> 4) << 3) + (lane & 7)) * 112
            + ks*32 + ((lane >> 3) & 1) * 16;
        ldm_x4(&bfr[nt * 4], addr);
      }
      #pragma unroll
      for (int mt = 0; mt < MT; ++mt)
        #pragma unroll
        for (int nt = 0; nt < NT8; ++nt)
          mma16816(acc[mt][nt], afr[mt], &bfr[nt * 2]);
    }
  }

  // epilogue
  const int r0 = lane >> 2;
  const int c2 = (lane & 3) * 2;
  #pragma unroll
  for (int mt = 0; mt < MT; ++mt) {
    #pragma unroll
    for (int nt = 0; nt < NT8; ++nt) {
      const int col = jb + wn*TN + nt*8 + c2;
      if (col < NOUT) {
        const int zr = zb + wm*TM + mt*16 + r0;
        *(float2*)&out[(size_t)zr * NOUT + col] =
            make_float2(acc[mt][nt][0], acc[mt][nt][1]);
        *(float2*)&out[(size_t)(zr + 8) * NOUT + col] =
            make_float2(acc[mt][nt][2], acc[mt][nt][3]);
      }
    }
  }
}

__global__ void __launch_bounds__(256)
mma_kernel(float* __restrict__ out) {
  extern __shared__ char smem[];
  const int zb = blockIdx.y * 128;
  if (blockIdx.x < 2) {
    mma_body<128, 2, 4>(out, blockIdx.x * 128, zb, smem);
  } else {
    mma_body<96, 4, 2>(out, 256, zb, smem);
  }
}

// ---------------------------------------------------------------------------
extern "C" void kernel_launch(void* const* d_in, const int* in_sizes, int n_in,
                              void* d_out, int out_size) {
  const float* r  = (const float*)d_in[0];
  const float* W1 = (const float*)d_in[1];
  const float* b1 = (const float*)d_in[2];
  const float* W2 = (const float*)d_in[3];
  const float* b2 = (const float*)d_in[4];
  const float* cg = (const float*)d_in[5];
  float* out = (float*)d_out;

  const int smem1 = (4352 + 3840 + 128 + 8448) * 4;       // 67072 B
  const int smemM = STGN * (ABUF + 128 * 112);            // 86016 B
  cudaFuncSetAttribute(feat_kernel,
      cudaFuncAttributeMaxDynamicSharedMemorySize, smem1);
  cudaFuncSetAttribute(mma_kernel,
      cudaFuncAttributeMaxDynamicSharedMemorySize, smemM);

  feat_kernel<<<ZTOT/128, 128, smem1>>>(r, W1, b1, W2, b2);
  prepB_kernel<<<NBP, 224>>>(cg);
  mma_kernel<<<dim3(3, ZTOT/128), 256, smemM>>>(out);
}

// round 16
// speedup vs baseline: 1.5453x; 1.1381x over previous
#include <cuda_runtime.h>
#include <cuda_fp16.h>
#include <math.h>
#include <stdint.h>

#define ZTOT  65536
#define KTOT  204
#define NPATH 60
#define NOUT  324
#define SEGP  208            // per-segment padding (204 + 4)
#define KP2   416            // K' = 2 * 208 (fp16 2-term split)
#define CH    32             // k' per chunk
#define NCH   13             // 416 / 32
#define NBP   384
#define STGN  3
#define ABUF  10240          // 128 * 80

// ---------------- scratch ----------------
__device__ uint4 g_Fhi4[(size_t)ZTOT * 32];           // [z][256] fp16 hi plane
__device__ uint4 g_Flo4[(size_t)ZTOT * 32];           // [z][256] fp16 lo plane
__device__ __align__(16) __half g_B[NBP * KP2];       // [n][416] C fp16 (dup segs)

// ---------------- helpers ----------------
__device__ __forceinline__ uint32_t smem_u32(const void* p) {
  uint32_t a;
  asm("{ .reg .u64 t; cvta.to.shared.u64 t, %1; cvt.u32.u64 %0, t; }"
      : "=r"(a) : "l"(p));
  return a;
}
__device__ __forceinline__ void cp16(uint32_t smaddr, const void* gptr) {
  asm volatile("cp.async.cg.shared.global [%0], [%1], 16;"
               :: "r"(smaddr), "l"(gptr) : "memory");
}
__device__ __forceinline__ void ldm_x4(uint32_t* r, uint32_t addr) {
  asm volatile("ldmatrix.sync.aligned.m8n8.x4.shared.b16 {%0,%1,%2,%3}, [%4];"
               : "=r"(r[0]), "=r"(r[1]), "=r"(r[2]), "=r"(r[3]) : "r"(addr));
}
__device__ __forceinline__ void mma16816(float* d, const uint32_t* a,
                                         const uint32_t* b) {
  asm volatile(
      "mma.sync.aligned.m16n8k16.row.col.f32.f16.f16.f32 "
      "{%0,%1,%2,%3}, {%4,%5,%6,%7}, {%8,%9}, {%0,%1,%2,%3};"
      : "+f"(d[0]), "+f"(d[1]), "+f"(d[2]), "+f"(d[3])
      : "r"(a[0]), "r"(a[1]), "r"(a[2]), "r"(a[3]), "r"(b[0]), "r"(b[1]));
}
__device__ __forceinline__ unsigned long long ffma2(unsigned long long a,
                                                    unsigned long long b,
                                                    unsigned long long c) {
  unsigned long long d;
  asm("fma.rn.f32x2 %0, %1, %2, %3;" : "=l"(d) : "l"(a), "l"(b), "l"(c));
  return d;
}
__device__ __forceinline__ unsigned long long pack2(float lo, float hi) {
  unsigned long long d;
  asm("mov.b64 %0, {%1, %2};" : "=l"(d) : "f"(lo), "f"(hi));
  return d;
}
__device__ __forceinline__ void unpack2(float& lo, float& hi,
                                        unsigned long long v) {
  asm("mov.b64 {%0, %1}, %2;" : "=f"(lo), "=f"(hi) : "l"(v));
}

// ---------------------------------------------------------------------------
// Kernel 1 (fused): radial MLP + SH -> fp16 hi/lo planes [z][256].
// ---------------------------------------------------------------------------
__global__ __launch_bounds__(128, 3) void feat_kernel(
    const float* __restrict__ r,  const float* __restrict__ W1,
    const float* __restrict__ b1, const float* __restrict__ W2,
    const float* __restrict__ b2) {
  extern __shared__ float sm[];
  float* sW1t = sm;                      // [64][68] transposed
  float* sW2  = sm + 4352;               // [64][60]
  float* sb1  = sm + 8192;
  float* sb2  = sm + 8256;
  float* sB   = sm + 8320;               // union: basis [64][128] / staging
  uint32_t* stg = (uint32_t*)sB;         // 2 planes x [128][33] uint32
  const int tid = threadIdx.x;

  #pragma unroll
  for (int i = 0; i < 32; ++i) {
    int idx = tid + i * 128;
    int j = idx >> 6, h = idx & 63;
    sW1t[h * 68 + j] = W1[idx];
  }
  #pragma unroll
  for (int i = 0; i < 30; ++i) sW2[tid + i*128] = W2[tid + i*128];
  if (tid < 64) sb1[tid] = b1[tid];
  if (tid < 60) sb2[tid] = b2[tid];
  __syncthreads();

  const int zb = blockIdx.x * 128;
  const int z = zb + tid;
  const float rx = r[3*z+0], ry = r[3*z+1], rz = r[3*z+2];
  const float rad = sqrtf(rx*rx + ry*ry + rz*rz);
  const float inv = 1.0f / (rad + 1e-12f);
  const float x = rx*inv, y = ry*inv, zc = rz*inv;

  float Y[9];
  Y[0] = 0.28209479177387814f;
  Y[1] = 0.4886025119029199f * y;
  Y[2] = 0.4886025119029199f * zc;
  Y[3] = 0.4886025119029199f * x;
  Y[4] = 1.0925484305920792f * x * y;
  Y[5] = 1.0925484305920792f * y * zc;
  Y[6] = 0.31539156525252005f * (3.0f*zc*zc - 1.0f);
  Y[7] = 1.0925484305920792f * x * zc;
  Y[8] = 0.5462742152960396f * (x*x - y*y);

  {  // radial basis, factorized (3 expf)
    const float DLT = 3.5f / 63.0f;
    int m = (int)floorf(rad / DLT + 0.5f);
    m = (m < 0) ? 0 : ((m > 63) ? 63 : m);
    const float u = rad - DLT * (float)m;
    const float A   = expf(-4.0f * u * u);
    const float tdn = expf(-0.44444444f * u);
    const float tup = expf( 0.44444444f * u);
    const float G1 = 0.98773021f;
    const float W  = 0.97561098f;
    sB[m*128 + tid] = A;
    float P = A, q = tdn * G1;
    for (int j = m - 1; j >= 0; --j) { P *= q; q *= W; sB[j*128 + tid] = P; }
    P = A; q = tup * G1;
    for (int j = m + 1; j < 64; ++j) { P *= q; q *= W; sB[j*128 + tid] = P; }
  }
  __syncthreads();

  unsigned long long Bu[32];
  #pragma unroll
  for (int q = 0; q < 32; ++q)
    Bu[q] = pack2(sB[(2*q)*128 + tid], sB[(2*q+1)*128 + tid]);

  unsigned long long Ru[30];
  #pragma unroll
  for (int q = 0; q < 30; ++q) Ru[q] = pack2(sb2[2*q], sb2[2*q+1]);

  #pragma unroll 4
  for (int h = 0; h < 64; ++h) {
    unsigned long long aA = 0ull, aB = 0ull;
    const float bias = sb1[h];
    #pragma unroll
    for (int q = 0; q < 16; ++q) {
      ulonglong2 w = *(const ulonglong2*)&sW1t[h*68 + q*4];
      aA = ffma2(Bu[2*q],   w.x, aA);
      aB = ffma2(Bu[2*q+1], w.y, aB);
    }
    float f0, f1, f2, f3;
    unpack2(f0, f1, aA);
    unpack2(f2, f3, aB);
    const float a = fmaxf(bias + ((f0 + f1) + (f2 + f3)), 0.0f);
    const unsigned long long ap = pack2(a, a);
    #pragma unroll
    for (int q = 0; q < 15; ++q) {
      ulonglong2 w = *(const ulonglong2*)&sW2[h*60 + q*4];
      Ru[2*q]   = ffma2(ap, w.x, Ru[2*q]);
      Ru[2*q+1] = ffma2(ap, w.y, Ru[2*q+1]);
    }
  }

  float R[NPATH];
  #pragma unroll
  for (int q = 0; q < 30; ++q) unpack2(R[2*q], R[2*q+1], Ru[q]);

  constexpr int LF[15]   = {0,1,2,1,0,1,2,1,2,2,1,2,0,1,2};
  constexpr int GOFF[15] = {0,4,16,36,48,52,64,84,96,116,136,148,168,172,184};
  __half* stHi = (__half*)stg;                 // [128][66]
  __half* stLo = (__half*)(stg + 128*33);

  #pragma unroll
  for (int c = 0; c < 4; ++c) {
    __syncthreads();
    if (c == 3) {
      #pragma unroll
      for (int w = 6; w < 32; ++w) {
        stg[tid*33 + w] = 0u;
        stg[128*33 + tid*33 + w] = 0u;
      }
    }
    #pragma unroll
    for (int p = 0; p < NPATH; ++p) {
      const int l  = LF[p >> 2];
      const int yo = (l == 0) ? 0 : ((l == 1) ? 1 : 4);
      const int kb = GOFF[p >> 2] + (p & 3) * (2*l + 1);
      #pragma unroll
      for (int mm = 0; mm < 2*l + 1; ++mm) {
        const int k = kb + mm;
        if (k >= c*64 && k < c*64 + 64) {
          const int kk = k - c*64;
          float f = R[p] * Y[yo + mm];
          __half hi = __float2half(f);
          __half lo = __float2half(f - __half2float(hi));
          stHi[tid*66 + kk] = hi;
          stLo[tid*66 + kk] = lo;
        }
      }
    }
    __syncthreads();
    #pragma unroll
    for (int it = 0; it < 16; ++it) {
      int i = tid + it * 128;
      int plane = i >> 10;
      int j = i & 1023;
      int row = j >> 3, q = j & 7;
      const uint32_t* src = stg + plane*(128*33) + row*33 + q*4;
      uint4 v; v.x = src[0]; v.y = src[1]; v.z = src[2]; v.w = src[3];
      (plane ? g_Flo4 : g_Fhi4)[(size_t)(zb + row) * 32 + c*8 + q] = v;
    }
  }
}

// ---------------------------------------------------------------------------
// Kernel 2: pack B = cg^T fp16, duplicated in both 208-segments
// ---------------------------------------------------------------------------
__global__ void prepB_kernel(const float* __restrict__ cg) {
  const int n = blockIdx.x;
  for (int kp = threadIdx.x; kp < KP2; kp += blockDim.x) {
    const int k = (kp >= SEGP) ? (kp - SEGP) : kp;
    float v = (n < NOUT && k < KTOT) ? cg[k * NOUT + n] : 0.0f;
    g_B[n * KP2 + kp] = __float2half(v);
  }
}

// ---------------------------------------------------------------------------
// Kernel 3: merged GEMM. One launch, grid (3, Z/128), 256 threads.
// bx 0,1 -> BC=128, warps 2x4 (tile 64x32); bx 2 -> BC=96, warps 4x2
// (tile 32x48). K'=416, 13 chunks of k32, 80B rows, 3-stage cp.async ring.
// ---------------------------------------------------------------------------
template <int BC, int NWM, int NWN>
__device__ __forceinline__ void mma_body(float* __restrict__ out, int jb,
                                         int zb, char* smem) {
  constexpr int TM   = 128 / NWM;
  constexpr int TN   = BC / NWN;
  constexpr int MT   = TM / 16;
  constexpr int NT16 = TN / 16;
  constexpr int NT8  = TN / 8;
  constexpr int BBUF = BC * 80;
  constexpr int TOT  = (128 + BC) * 4;     // cp16 ops per chunk

  const uint32_t sb = smem_u32(smem);
  const int tid = threadIdx.x;
  const int w = tid >> 5, lane = tid & 31;
  const int wm = w / NWN, wn = w % NWN;

  auto issue = [&](int c, int buf) {
    const uint32_t base = sb + buf * (ABUF + BBUF);
    const char* Bb = (const char*)g_B;
    #pragma unroll
    for (int it = 0; it < (TOT + 255) / 256; ++it) {
      int i = tid + it * 256;
      if ((TOT % 256 == 0) || i < TOT) {
        int half = i >= 512;                 // 0: A (128 rows), 1: B (BC rows)
        int j = i - half * 512;
        int row = j >> 2, quad = j & 3;
        int kp = c * CH + quad * 8;
        uint32_t dst = base + half * ABUF + row * 80 + quad * 16;
        if (half) {
          cp16(dst, Bb + (size_t)(jb + row) * (KP2*2) + kp * 2);
        } else {
          int seg = (kp >= SEGP) ? 1 : 0;
          int kk = kp - seg * SEGP;
          const char* Asrc = (const char*)(seg ? g_Flo4 : g_Fhi4)
                             + (size_t)(zb + row) * 512 + kk * 2;
          cp16(dst, Asrc);
        }
      }
    }
    asm volatile("cp.async.commit_group;" ::: "memory");
  };

  float acc[MT][NT8][4];
  #pragma unroll
  for (int mt = 0; mt < MT; ++mt)
    #pragma unroll
    for (int nt = 0; nt < NT8; ++nt)
      #pragma unroll
      for (int q = 0; q < 4; ++q) acc[mt][nt][q] = 0.0f;

  issue(0, 0);
  issue(1, 1);

  for (int c = 0; c < NCH; ++c) {
    if (c >= NCH - 2)
      asm volatile("cp.async.wait_group 0;" ::: "memory");
    else
      asm volatile("cp.async.wait_group 1;" ::: "memory");
    __syncthreads();

    if (c + 2 < NCH) issue(c + 2, (c + 2) % STGN);

    const uint32_t aBase = sb + (c % STGN) * (ABUF + BBUF);
    const uint32_t bBase = aBase + ABUF;

    #pragma unroll
    for (int ks = 0; ks < 2; ++ks) {
      uint32_t afr[MT][4];
      #pragma unroll
      for (int mt = 0; mt < MT; ++mt) {
        uint32_t addr = aBase + (wm*TM + mt*16 + (lane & 15)) * 80
                      + ks*32 + (lane >> 4) * 16;
        ldm_x4(afr[mt], addr);
      }
      uint32_t bfr[NT16 * 4];
      #pragma unroll
      for (int nt = 0; nt < NT16; ++nt) {
        uint32_t addr = bBase
            + (wn*TN + nt*16 + ((lane >> 4) << 3) + (lane & 7)) * 80
            + ks*32 + ((lane >> 3) & 1) * 16;
        ldm_x4(&bfr[nt * 4], addr);
      }
      #pragma unroll
      for (int mt = 0; mt < MT; ++mt)
        #pragma unroll
        for (int nt = 0; nt < NT8; ++nt)
          mma16816(acc[mt][nt], afr[mt], &bfr[nt * 2]);
    }
  }

  // epilogue
  const int r0 = lane >> 2;
  const int c2 = (lane & 3) * 2;
  #pragma unroll
  for (int mt = 0; mt < MT; ++mt) {
    #pragma unroll
    for (int nt = 0; nt < NT8; ++nt) {
      const int col = jb + wn*TN + nt*8 + c2;
      if (col < NOUT) {
        const int zr = zb + wm*TM + mt*16 + r0;
        *(float2*)&out[(size_t)zr * NOUT + col] =
            make_float2(acc[mt][nt][0], acc[mt][nt][1]);
        *(float2*)&out[(size_t)(zr + 8) * NOUT + col] =
            make_float2(acc[mt][nt][2], acc[mt][nt][3]);
      }
    }
  }
}

__global__ void __launch_bounds__(256)
mma_kernel(float* __restrict__ out) {
  extern __shared__ char smem[];
  const int zb = blockIdx.y * 128;
  if (blockIdx.x < 2) {
    mma_body<128, 2, 4>(out, blockIdx.x * 128, zb, smem);
  } else {
    mma_body<96, 4, 2>(out, 256, zb, smem);
  }
}

// ---------------------------------------------------------------------------
extern "C" void kernel_launch(void* const* d_in, const int* in_sizes, int n_in,
                              void* d_out, int out_size) {
  const float* r  = (const float*)d_in[0];
  const float* W1 = (const float*)d_in[1];
  const float* b1 = (const float*)d_in[2];
  const float* W2 = (const float*)d_in[3];
  const float* b2 = (const float*)d_in[4];
  const float* cg = (const float*)d_in[5];
  float* out = (float*)d_out;

  const int smem1 = (4352 + 3840 + 128 + 8448) * 4;       // 67072 B
  const int smemM = STGN * (ABUF + 128 * 80);             // 61440 B
  cudaFuncSetAttribute(feat_kernel,
      cudaFuncAttributeMaxDynamicSharedMemorySize, smem1);
  cudaFuncSetAttribute(mma_kernel,
      cudaFuncAttributeMaxDynamicSharedMemorySize, smemM);

  feat_kernel<<<ZTOT/128, 128, smem1>>>(r, W1, b1, W2, b2);
  prepB_kernel<<<NBP, 224>>>(cg);
  mma_kernel<<<dim3(3, ZTOT/128), 256, smemM>>>(out);
}

// round 17
// speedup vs baseline: 1.5490x; 1.0024x over previous
#include <cuda_runtime.h>
#include <cuda_fp16.h>
#include <math.h>
#include <stdint.h>

#define ZTOT  65536
#define KTOT  204
#define NPATH 60
#define NOUT  324
#define SEGP  208            // per-segment padding (204 + 4)
#define KP2   416            // K' = 2 * 208 (fp16 2-term split)
#define CH    64             // k' per chunk
#define NCH   7              // 6 full + 1 half (416 = 6*64 + 32)
#define NBP   384
#define STGN  3
#define ABUF  18432          // 128 * 144

// ---------------- scratch ----------------
__device__ uint4 g_Fhi4[(size_t)ZTOT * 32];           // [z][256] fp16 hi plane
__device__ uint4 g_Flo4[(size_t)ZTOT * 32];           // [z][256] fp16 lo plane
__device__ __align__(16) __half g_B[NBP * KP2];       // [n][416] C fp16 (dup segs)

// k -> (path, ylm) inverse map, built at compile time.
struct KMap {
  int p[256]; int y[256];
  constexpr KMap() : p(), y() {
    for (int i = 0; i < 256; ++i) { p[i] = -1; y[i] = 0; }
    const int LFa[15] = {0,1,2,1,0,1,2,1,2,2,1,2,0,1,2};
    int k = 0;
    for (int b = 0; b < 15; ++b)
      for (int m4 = 0; m4 < 4; ++m4) {
        int l = LFa[b];
        int yo = (l == 0) ? 0 : ((l == 1) ? 1 : 4);
        for (int mm = 0; mm < 2*l + 1; ++mm) { p[k] = b*4 + m4; y[k] = yo + mm; ++k; }
      }
  }
};

// ---------------- helpers ----------------
__device__ __forceinline__ uint32_t smem_u32(const void* p) {
  uint32_t a;
  asm("{ .reg .u64 t; cvta.to.shared.u64 t, %1; cvt.u32.u64 %0, t; }"
      : "=r"(a) : "l"(p));
  return a;
}
__device__ __forceinline__ void cp16(uint32_t smaddr, const void* gptr) {
  asm volatile("cp.async.cg.shared.global [%0], [%1], 16;"
               :: "r"(smaddr), "l"(gptr) : "memory");
}
__device__ __forceinline__ void ldm_x4(uint32_t* r, uint32_t addr) {
  asm volatile("ldmatrix.sync.aligned.m8n8.x4.shared.b16 {%0,%1,%2,%3}, [%4];"
               : "=r"(r[0]), "=r"(r[1]), "=r"(r[2]), "=r"(r[3]) : "r"(addr));
}
__device__ __forceinline__ void mma16816(float* d, const uint32_t* a,
                                         const uint32_t* b) {
  asm volatile(
      "mma.sync.aligned.m16n8k16.row.col.f32.f16.f16.f32 "
      "{%0,%1,%2,%3}, {%4,%5,%6,%7}, {%8,%9}, {%0,%1,%2,%3};"
      : "+f"(d[0]), "+f"(d[1]), "+f"(d[2]), "+f"(d[3])
      : "r"(a[0]), "r"(a[1]), "r"(a[2]), "r"(a[3]), "r"(b[0]), "r"(b[1]));
}
__device__ __forceinline__ unsigned long long ffma2(unsigned long long a,
                                                    unsigned long long b,
                                                    unsigned long long c) {
  unsigned long long d;
  asm("fma.rn.f32x2 %0, %1, %2, %3;" : "=l"(d) : "l"(a), "l"(b), "l"(c));
  return d;
}
__device__ __forceinline__ unsigned long long pack2(float lo, float hi) {
  unsigned long long d;
  asm("mov.b64 %0, {%1, %2};" : "=l"(d) : "f"(lo), "f"(hi));
  return d;
}
__device__ __forceinline__ void unpack2(float& lo, float& hi,
                                        unsigned long long v) {
  asm("mov.b64 {%0, %1}, %2;" : "=f"(lo), "=f"(hi) : "l"(v));
}

// ---------------------------------------------------------------------------
// Kernel 1 (fused): radial MLP + SH -> fp16 hi/lo planes [z][256].
// No staging: per-thread contiguous STG.128 rows; one syncthreads total.
// ---------------------------------------------------------------------------
__global__ __launch_bounds__(128, 3) void feat_kernel(
    const float* __restrict__ r,  const float* __restrict__ W1,
    const float* __restrict__ b1, const float* __restrict__ W2,
    const float* __restrict__ b2) {
  extern __shared__ float sm[];
  float* sW1t = sm;                      // [64][68] transposed
  float* sW2  = sm + 4352;               // [64][60]
  float* sb1  = sm + 8192;
  float* sb2  = sm + 8256;
  float* sB   = sm + 8320;               // basis [64][128]
  const int tid = threadIdx.x;

  #pragma unroll
  for (int i = 0; i < 32; ++i) {
    int idx = tid + i * 128;
    int j = idx >> 6, h = idx & 63;
    sW1t[h * 68 + j] = W1[idx];
  }
  #pragma unroll
  for (int i = 0; i < 30; ++i) sW2[tid + i*128] = W2[tid + i*128];
  if (tid < 64) sb1[tid] = b1[tid];
  if (tid < 60) sb2[tid] = b2[tid];
  __syncthreads();

  const int z = blockIdx.x * 128 + tid;
  const float rx = r[3*z+0], ry = r[3*z+1], rz = r[3*z+2];
  const float rad = sqrtf(rx*rx + ry*ry + rz*rz);
  const float inv = 1.0f / (rad + 1e-12f);
  const float x = rx*inv, y = ry*inv, zc = rz*inv;

  float Y[9];
  Y[0] = 0.28209479177387814f;
  Y[1] = 0.4886025119029199f * y;
  Y[2] = 0.4886025119029199f * zc;
  Y[3] = 0.4886025119029199f * x;
  Y[4] = 1.0925484305920792f * x * y;
  Y[5] = 1.0925484305920792f * y * zc;
  Y[6] = 0.31539156525252005f * (3.0f*zc*zc - 1.0f);
  Y[7] = 1.0925484305920792f * x * zc;
  Y[8] = 0.5462742152960396f * (x*x - y*y);

  {  // radial basis, factorized (3 expf); per-thread column, no sync needed
    const float DLT = 3.5f / 63.0f;
    int m = (int)floorf(rad / DLT + 0.5f);
    m = (m < 0) ? 0 : ((m > 63) ? 63 : m);
    const float u = rad - DLT * (float)m;
    const float A   = expf(-4.0f * u * u);
    const float tdn = expf(-0.44444444f * u);
    const float tup = expf( 0.44444444f * u);
    const float G1 = 0.98773021f;
    const float W  = 0.97561098f;
    sB[m*128 + tid] = A;
    float P = A, q = tdn * G1;
    for (int j = m - 1; j >= 0; --j) { P *= q; q *= W; sB[j*128 + tid] = P; }
    P = A; q = tup * G1;
    for (int j = m + 1; j < 64; ++j) { P *= q; q *= W; sB[j*128 + tid] = P; }
  }

  unsigned long long Bu[32];
  #pragma unroll
  for (int q = 0; q < 32; ++q)
    Bu[q] = pack2(sB[(2*q)*128 + tid], sB[(2*q+1)*128 + tid]);

  unsigned long long Ru[30];
  #pragma unroll
  for (int q = 0; q < 30; ++q) Ru[q] = pack2(sb2[2*q], sb2[2*q+1]);

  #pragma unroll 4
  for (int h = 0; h < 64; ++h) {
    unsigned long long aA = 0ull, aB = 0ull;
    const float bias = sb1[h];
    #pragma unroll
    for (int q = 0; q < 16; ++q) {
      ulonglong2 w = *(const ulonglong2*)&sW1t[h*68 + q*4];
      aA = ffma2(Bu[2*q],   w.x, aA);
      aB = ffma2(Bu[2*q+1], w.y, aB);
    }
    float f0, f1, f2, f3;
    unpack2(f0, f1, aA);
    unpack2(f2, f3, aB);
    const float a = fmaxf(bias + ((f0 + f1) + (f2 + f3)), 0.0f);
    const unsigned long long ap = pack2(a, a);
    #pragma unroll
    for (int q = 0; q < 15; ++q) {
      ulonglong2 w = *(const ulonglong2*)&sW2[h*60 + q*4];
      Ru[2*q]   = ffma2(ap, w.x, Ru[2*q]);
      Ru[2*q+1] = ffma2(ap, w.y, Ru[2*q+1]);
    }
  }

  float R[NPATH];
  #pragma unroll
  for (int q = 0; q < 30; ++q) unpack2(R[2*q], R[2*q+1], Ru[q]);

  // emit fp16 hi/lo planes: per-chunk uint4 assembly, direct STG.128.
  constexpr KMap KM{};
  #pragma unroll
  for (int c = 0; c < 4; ++c) {
    #pragma unroll
    for (int q = 0; q < 8; ++q) {
      uint32_t hw[4], lw[4];
      #pragma unroll
      for (int s = 0; s < 4; ++s) {
        const int k0 = c*64 + q*8 + 2*s;
        const int k1 = k0 + 1;
        float f0 = (KM.p[k0] >= 0) ? R[KM.p[k0]] * Y[KM.y[k0]] : 0.0f;
        float f1 = (KM.p[k1] >= 0) ? R[KM.p[k1]] * Y[KM.y[k1]] : 0.0f;
        __half h0 = __float2half(f0), h1 = __float2half(f1);
        __half l0 = __float2half(f0 - __half2float(h0));
        __half l1 = __float2half(f1 - __half2float(h1));
        hw[s] = (uint32_t)__half_as_ushort(h0) |
                ((uint32_t)__half_as_ushort(h1) << 16);
        lw[s] = (uint32_t)__half_as_ushort(l0) |
                ((uint32_t)__half_as_ushort(l1) << 16);
      }
      g_Fhi4[(size_t)z * 32 + c*8 + q] = make_uint4(hw[0], hw[1], hw[2], hw[3]);
      g_Flo4[(size_t)z * 32 + c*8 + q] = make_uint4(lw[0], lw[1], lw[2], lw[3]);
    }
  }
}

// ---------------------------------------------------------------------------
// Kernel 2: pack B = cg^T fp16, duplicated in both 208-segments
// ---------------------------------------------------------------------------
__global__ void prepB_kernel(const float* __restrict__ cg) {
  const int n = blockIdx.x;
  for (int kp = threadIdx.x; kp < KP2; kp += blockDim.x) {
    const int k = (kp >= SEGP) ? (kp - SEGP) : kp;
    float v = (n < NOUT && k < KTOT) ? cg[k * NOUT + n] : 0.0f;
    g_B[n * KP2 + kp] = __float2half(v);
  }
}

// ---------------------------------------------------------------------------
// Kernel 3: merged GEMM. One launch, grid (3, Z/128), 256 threads.
// bx 0,1 -> BC=128, warps 2x4 (tile 64x32); bx 2 -> BC=96, warps 4x2
// (tile 32x48). K'=416: 6 chunks of k64 + 1 half chunk; 144B rows;
// 3-stage cp.async ring.
// ---------------------------------------------------------------------------
template <int BC, int NWM, int NWN>
__device__ __forceinline__ void mma_body(float* __restrict__ out, int jb,
                                         int zb, char* smem) {
  constexpr int TM   = 128 / NWM;
  constexpr int TN   = BC / NWN;
  constexpr int MT   = TM / 16;
  constexpr int NT16 = TN / 16;
  constexpr int NT8  = TN / 8;
  constexpr int BBUF = BC * 144;
  constexpr int TOT  = (128 + BC) * 8;     // cp16 slots per chunk

  const uint32_t sb = smem_u32(smem);
  const int tid = threadIdx.x;
  const int w = tid >> 5, lane = tid & 31;
  const int wm = w / NWN, wn = w % NWN;

  auto issue = [&](int c, int buf) {
    const uint32_t base = sb + buf * (ABUF + BBUF);
    const char* Bb = (const char*)g_B;
    #pragma unroll
    for (int it = 0; it < (TOT + 255) / 256; ++it) {
      int i = tid + it * 256;
      if ((TOT % 256 == 0) || i < TOT) {
        int half = i >= 1024;                // 0: A (128 rows), 1: B (BC rows)
        int j = i - half * 1024;
        int row = j >> 3, quad = j & 7;
        int kp = c * CH + quad * 8;
        if (kp < KP2) {
          uint32_t dst = base + half * ABUF + row * 144 + quad * 16;
          if (half) {
            cp16(dst, Bb + (size_t)(jb + row) * (KP2*2) + kp * 2);
          } else {
            int seg = (kp >= SEGP) ? 1 : 0;
            int kk = kp - seg * SEGP;
            const char* Asrc = (const char*)(seg ? g_Flo4 : g_Fhi4)
                               + (size_t)(zb + row) * 512 + kk * 2;
            cp16(dst, Asrc);
          }
        }
      }
    }
    asm volatile("cp.async.commit_group;" ::: "memory");
  };

  float acc[MT][NT8][4];
  #pragma unroll
  for (int mt = 0; mt < MT; ++mt)
    #pragma unroll
    for (int nt = 0; nt < NT8; ++nt)
      #pragma unroll
      for (int q = 0; q < 4; ++q) acc[mt][nt][q] = 0.0f;

  issue(0, 0);
  issue(1, 1);

  auto compute = [&](int c, int nks) {
    const uint32_t aBase = sb + (c % STGN) * (ABUF + BBUF);
    const uint32_t bBase = aBase + ABUF;
    #pragma unroll 4
    for (int ks = 0; ks < nks; ++ks) {
      uint32_t afr[MT][4];
      #pragma unroll
      for (int mt = 0; mt < MT; ++mt) {
        uint32_t addr = aBase + (wm*TM + mt*16 + (lane & 15)) * 144
                      + ks*32 + (lane >> 4) * 16;
        ldm_x4(afr[mt], addr);
      }
      uint32_t bfr[NT16 * 4];
      #pragma unroll
      for (int nt = 0; nt < NT16; ++nt) {
        uint32_t addr = bBase
            + (wn*TN + nt*16 + ((lane >> 4) << 3) + (lane & 7)) * 144
            + ks*32 + ((lane >> 3) & 1) * 16;
        ldm_x4(&bfr[nt * 4], addr);
      }
      #pragma unroll
      for (int mt = 0; mt < MT; ++mt)
        #pragma unroll
        for (int nt = 0; nt < NT8; ++nt)
          mma16816(acc[mt][nt], afr[mt], &bfr[nt * 2]);
    }
  };

  for (int c = 0; c < NCH; ++c) {
    if (c >= NCH - 2)
      asm volatile("cp.async.wait_group 0;" ::: "memory");
    else
      asm volatile("cp.async.wait_group 1;" ::: "memory");
    __syncthreads();

    if (c + 2 < NCH) issue(c + 2, (c + 2) % STGN);

    compute(c, (c == NCH - 1) ? 2 : 4);
  }

  // epilogue
  const int r0 = lane >> 2;
  const int c2 = (lane & 3) * 2;
  #pragma unroll
  for (int mt = 0; mt < MT; ++mt) {
    #pragma unroll
    for (int nt = 0; nt < NT8; ++nt) {
      const int col = jb + wn*TN + nt*8 + c2;
      if (col < NOUT) {
        const int zr = zb + wm*TM + mt*16 + r0;
        *(float2*)&out[(size_t)zr * NOUT + col] =
            make_float2(acc[mt][nt][0], acc[mt][nt][1]);
        *(float2*)&out[(size_t)(zr + 8) * NOUT + col] =
            make_float2(acc[mt][nt][2], acc[mt][nt][3]);
      }
    }
  }
}

__global__ void __launch_bounds__(256)
mma_kernel(float* __restrict__ out) {
  extern __shared__ char smem[];
  const int zb = blockIdx.y * 128;
  if (blockIdx.x < 2) {
    mma_body<128, 2, 4>(out, blockIdx.x * 128, zb, smem);
  } else {
    mma_body<96, 4, 2>(out, 256, zb, smem);
  }
}

// ---------------------------------------------------------------------------
extern "C" void kernel_launch(void* const* d_in, const int* in_sizes, int n_in,
                              void* d_out, int out_size) {
  const float* r  = (const float*)d_in[0];
  const float* W1 = (const float*)d_in[1];
  const float* b1 = (const float*)d_in[2];
  const float* W2 = (const float*)d_in[3];
  const float* b2 = (const float*)d_in[4];
  const float* cg = (const float*)d_in[5];
  float* out = (float*)d_out;

  const int smem1 = (4352 + 3840 + 128 + 8192) * 4;       // 66048 B
  const int smemM = STGN * (ABUF + 128 * 144);            // 110592 B
  cudaFuncSetAttribute(feat_kernel,
      cudaFuncAttributeMaxDynamicSharedMemorySize, smem1);
  cudaFuncSetAttribute(mma_kernel,
      cudaFuncAttributeMaxDynamicSharedMemorySize, smemM);

  feat_kernel<<<ZTOT/128, 128, smem1>>>(r, W1, b1, W2, b2);
  prepB_kernel<<<NBP, 224>>>(cg);
  mma_kernel<<<dim3(3, ZTOT/128), 256, smemM>>>(out);
}